// round 15
// baseline (speedup 1.0000x reference)
#include <cuda_runtime.h>
#include <cuda_fp16.h>
#include <math.h>
#include <stdint.h>

#define BB   2
#define TTOK 2048
#define DDIM 1024
#define NH   16
#define HDIM 64
#define BT   (BB*TTOK)   // 4096

// scratch (static device arrays)
__device__ float  g_x1 [BT * DDIM];
__device__ __half g_a16[BT * DDIM];
__device__ __half g_qv16[BT * 3 * DDIM];
__device__ __half g_h16[BT * 4 * DDIM];
__device__ __half g_wq16[3 * DDIM * DDIM];   // [K,N] fp16 weights
__device__ __half g_wo16[DDIM * DDIM];
__device__ __half g_w116[4 * DDIM * DDIM];
__device__ __half g_w216[4 * DDIM * DDIM];

__device__ __forceinline__ uint32_t s2u(const void* p) {
    uint32_t a;
    asm("{ .reg .u64 t; cvta.to.shared.u64 t, %1; cvt.u32.u64 %0, t; }" : "=r"(a) : "l"(p));
    return a;
}
__device__ __forceinline__ void cp16(uint32_t dst, const void* src) {
    asm volatile("cp.async.cg.shared.global [%0], [%1], 16;" :: "r"(dst), "l"(src));
}
#define CP_COMMIT() asm volatile("cp.async.commit_group;" ::: "memory")
#define CP_WAIT0()  asm volatile("cp.async.wait_group 0;" ::: "memory")
#define CP_WAIT1()  asm volatile("cp.async.wait_group 1;" ::: "memory")

__device__ __forceinline__ void ldsm4(uint32_t* r, uint32_t addr) {
    asm volatile("ldmatrix.sync.aligned.m8n8.x4.shared.b16 {%0,%1,%2,%3}, [%4];"
                 : "=r"(r[0]), "=r"(r[1]), "=r"(r[2]), "=r"(r[3]) : "r"(addr));
}
__device__ __forceinline__ void ldsm4t(uint32_t* r, uint32_t addr) {
    asm volatile("ldmatrix.sync.aligned.m8n8.x4.trans.shared.b16 {%0,%1,%2,%3}, [%4];"
                 : "=r"(r[0]), "=r"(r[1]), "=r"(r[2]), "=r"(r[3]) : "r"(addr));
}
__device__ __forceinline__ void mma_f16(float* c, const uint32_t* a,
                                        uint32_t b0, uint32_t b1) {
    asm("mma.sync.aligned.m16n8k16.row.col.f32.f16.f16.f32 "
        "{%0,%1,%2,%3}, {%4,%5,%6,%7}, {%8,%9}, {%0,%1,%2,%3};"
        : "+f"(c[0]), "+f"(c[1]), "+f"(c[2]), "+f"(c[3])
        : "r"(a[0]), "r"(a[1]), "r"(a[2]), "r"(a[3]), "r"(b0), "r"(b1));
}
__device__ __forceinline__ uint32_t ex2_h2(float a0, float a1) {
    __half2 h = __floats2half2_rn(a0, a1);
    uint32_t r;
    asm("ex2.approx.f16x2 %0, %1;" : "=r"(r) : "r"(*(uint32_t*)&h));
    return r;
}

__device__ __forceinline__ float gelu_f(float x) {
    float x3 = x * x * x;
    return 0.5f * x * (1.0f + tanhf(0.7978845608028654f * (x + 0.044715f * x3)));
}

// streaming fp32 -> fp16 convert
__global__ void wconv16(const float* __restrict__ W, __half* __restrict__ O, int n8) {
    int idx = blockIdx.x * 256 + threadIdx.x;
    if (idx >= n8) return;
    size_t base = (size_t)idx * 8;
    float4 a = *(const float4*)(W + base);
    float4 b = *(const float4*)(W + base + 4);
    __half2 h[4];
    h[0] = __floats2half2_rn(a.x, a.y);
    h[1] = __floats2half2_rn(a.z, a.w);
    h[2] = __floats2half2_rn(b.x, b.y);
    h[3] = __floats2half2_rn(b.z, b.w);
    *(uint4*)(O + base) = *(uint4*)h;
}

// LayerNorm -> fp16
__global__ void ln_h(const float* __restrict__ x, const float* __restrict__ g,
                     const float* __restrict__ b, __half* __restrict__ o) {
    int row = blockIdx.x;
    int tid = threadIdx.x;
    float4 v = ((const float4*)(x + (size_t)row * DDIM))[tid];
    float s  = v.x + v.y + v.z + v.w;
    float ss = v.x*v.x + v.y*v.y + v.z*v.z + v.w*v.w;
    #pragma unroll
    for (int off = 16; off > 0; off >>= 1) {
        s  += __shfl_xor_sync(0xffffffffu, s,  off);
        ss += __shfl_xor_sync(0xffffffffu, ss, off);
    }
    __shared__ float rs[8], rss[8];
    int w = tid >> 5, ln = tid & 31;
    if (ln == 0) { rs[w] = s; rss[w] = ss; }
    __syncthreads();
    float tot = 0.f, tots = 0.f;
    #pragma unroll
    for (int i = 0; i < 8; i++) { tot += rs[i]; tots += rss[i]; }
    float mu  = tot * (1.0f / DDIM);
    float var = tots * (1.0f / DDIM) - mu * mu;
    float inv = rsqrtf(var + 1e-5f);
    float4 gg = ((const float4*)g)[tid];
    float4 bb = ((const float4*)b)[tid];
    float r0 = (v.x - mu) * inv * gg.x + bb.x;
    float r1 = (v.y - mu) * inv * gg.y + bb.y;
    float r2 = (v.z - mu) * inv * gg.z + bb.z;
    float r3 = (v.w - mu) * inv * gg.w + bb.w;
    size_t base = (size_t)row * DDIM + tid * 4;
    *(__half2*)(o + base)     = __floats2half2_rn(r0, r1);
    *(__half2*)(o + base + 2) = __floats2half2_rn(r2, r3);
}

// HMMA fp16 GEMM: C[M,N] = A[M,K] @ B[K,N] + bias   (B in [K,N] row-major)
// 128x256 block, 8 warps (2Mx4N), warp 64x64, K-chunk 128, 2-stage cp.async,
// manual fragment double-buffering across k16 steps.
#define AROWB  272
#define BROWB  528
#define OFF_A  0
#define OFF_B  (128*272)
#define STG    (128*272 + 128*528)       // 102400
#define GEMM_SMEM (2 * STG)              // 204800

__device__ __forceinline__ void load_stage(
    uint32_t st, const __half* __restrict__ A, const __half* __restrict__ B,
    int N, int K, int bm, int bn, int k0, int tid)
{
    #pragma unroll
    for (int j = 0; j < 8; j++) {
        int o = tid + (j << 8);
        int r = o >> 4, c = o & 15;
        cp16(st + OFF_A + (uint32_t)(r * AROWB + (c << 4)),
             A + (size_t)(bm + r) * K + k0 + (c << 3));
    }
    #pragma unroll
    for (int j = 0; j < 16; j++) {
        int o = tid + (j << 8);
        int r = o >> 5, c = o & 31;
        cp16(st + OFF_B + (uint32_t)(r * BROWB + (c << 4)),
             B + (size_t)(k0 + r) * N + bn + (c << 3));
    }
}

__device__ __forceinline__ void load_frags(
    uint32_t st, int ks, int wm, int wn, int arow, int acol, int bg, int brow,
    uint32_t aF[4][4], uint32_t bF[8][2])
{
    #pragma unroll
    for (int mi = 0; mi < 4; mi++) {
        uint32_t off = (uint32_t)(((wm << 6) + (mi << 4) + arow) * AROWB
                                  + ((ks << 4) + acol) * 2);
        ldsm4(aF[mi], st + OFF_A + off);
    }
    #pragma unroll
    for (int np = 0; np < 4; np++) {
        uint32_t off = (uint32_t)(((ks << 4) + ((bg & 1) << 3) + brow) * BROWB
                                  + ((wn << 6) + (np << 4) + ((bg >> 1) << 3)) * 2);
        uint32_t r[4];
        ldsm4t(r, st + OFF_B + off);
        bF[2*np][0]   = r[0]; bF[2*np][1]   = r[1];
        bF[2*np+1][0] = r[2]; bF[2*np+1][1] = r[3];
    }
}

template<int EPI>
__global__ void __launch_bounds__(256, 1) hmma_gemm(
    const __half* __restrict__ A, const __half* __restrict__ B,
    const float* __restrict__ bias, const float* __restrict__ res,
    float* __restrict__ Cf, __half* __restrict__ Ch, int N, int K)
{
    extern __shared__ __align__(1024) char smem[];
    uint32_t sb = s2u(smem);
    int tid = threadIdx.x, wid = tid >> 5, lane = tid & 31;
    int wm = wid & 1, wn = wid >> 1;
    int bm = blockIdx.y << 7, bn = blockIdx.x << 8;

    float acc[4][8][4];
    #pragma unroll
    for (int mi = 0; mi < 4; mi++)
        #pragma unroll
        for (int ni = 0; ni < 8; ni++)
            #pragma unroll
            for (int e = 0; e < 4; e++) acc[mi][ni][e] = 0.f;

    int nch = K >> 7;
    load_stage(sb, A, B, N, K, bm, bn, 0, tid);
    CP_COMMIT();

    int arow = lane & 15;
    int acol = (lane >> 4) << 3;
    int bg   = lane >> 3;
    int brow = lane & 7;

    uint32_t aF[2][4][4], bF[2][8][2];

    for (int i = 0; i < nch; i++) {
        CP_WAIT0();
        __syncthreads();
        if (i + 1 < nch) {
            load_stage(sb + (uint32_t)((i + 1) & 1) * STG,
                       A, B, N, K, bm, bn, (i + 1) << 7, tid);
            CP_COMMIT();
        }
        uint32_t st = sb + (uint32_t)(i & 1) * STG;
        load_frags(st, 0, wm, wn, arow, acol, bg, brow, aF[0], bF[0]);
        #pragma unroll
        for (int ks = 0; ks < 8; ks++) {
            int cur = ks & 1;
            if (ks < 7)
                load_frags(st, ks + 1, wm, wn, arow, acol, bg, brow,
                           aF[cur ^ 1], bF[cur ^ 1]);
            #pragma unroll
            for (int mi = 0; mi < 4; mi++)
                #pragma unroll
                for (int ni = 0; ni < 8; ni++)
                    mma_f16(acc[mi][ni], aF[cur][mi], bF[cur][ni][0], bF[cur][ni][1]);
        }
    }

    __syncthreads();
    #pragma unroll
    for (int mi = 0; mi < 4; mi++) {
        #pragma unroll
        for (int ni = 0; ni < 8; ni++) {
            int row0 = bm + (wm << 6) + (mi << 4) + (lane >> 2);
            int col  = bn + (wn << 6) + (ni << 3) + ((lane & 3) << 1);
            float b0 = __ldg(bias + col), b1 = __ldg(bias + col + 1);
            #pragma unroll
            for (int hf = 0; hf < 2; hf++) {
                int row = row0 + hf * 8;
                float v0 = acc[mi][ni][hf * 2 + 0] + b0;
                float v1 = acc[mi][ni][hf * 2 + 1] + b1;
                size_t oi = (size_t)row * N + col;
                if (EPI == 2) {
                    float2 rv = *(const float2*)(res + oi);
                    float2 ov; ov.x = v0 + rv.x; ov.y = v1 + rv.y;
                    *(float2*)(Cf + oi) = ov;
                } else {
                    float a0 = (EPI == 1) ? gelu_f(v0) : v0;
                    float a1 = (EPI == 1) ? gelu_f(v1) : v1;
                    *(__half2*)(Ch + oi) = __floats2half2_rn(a0, a1);
                }
            }
        }
    }
}

// fp16 flash attention: BQ=128 (8 warps x 16 rows), BK=64, hd=64
// 2 CTAs/SM, 3-stage KV cp.async pipeline (full tile of load/compute overlap).
#define AQ_STRIDE 144
#define SM_Q   0
#define SM_KV0 18432
#define KV_STG 18432
#define VOFF   9216
#define ATT_SMEM (SM_KV0 + 3 * KV_STG)   // 73728

__device__ __forceinline__ void att_load_kv(
    uint32_t base, const __half* __restrict__ qv, size_t kvrow0, int tid)
{
    const size_t TD3 = 3 * DDIM;
    #pragma unroll
    for (int i = 0; i < 4; i++) {
        int e = tid + (i << 8);
        int t = e >> 9;               // 0 K, 1 V
        int rem = e & 511;
        int r = rem >> 3, c = rem & 7;
        size_t off = (kvrow0 + r) * TD3 + (t ? 2 * DDIM : DDIM) + (c << 3);
        cp16(base + (t ? (uint32_t)VOFF : 0u) + r * AQ_STRIDE + (c << 4), qv + off);
    }
}

__global__ void __launch_bounds__(256, 2) attn_tc(
    const __half* __restrict__ qv, __half* __restrict__ o16)
{
    extern __shared__ __align__(1024) char smem[];
    uint32_t sb = s2u(smem);
    int qt = (int)gridDim.x - 1 - (int)blockIdx.x;
    int b  = blockIdx.y >> 4;
    int h  = blockIdx.y & 15;
    int tid = threadIdx.x, wid = tid >> 5, lane = tid & 31;
    const size_t TD3 = 3 * DDIM;
    size_t qrow0 = (size_t)b * TTOK + (size_t)qt * 128;
    const __half* qv_head = qv + h * HDIM;
    const float L2E = 1.4426950408889634f;

    int ntiles = 2 * qt + 2;

    // Q tile + KV stages 0,1 (Q rides with stage-0's group)
    #pragma unroll
    for (int i = 0; i < 4; i++) {
        int e = tid + (i << 8);
        int r = e >> 3, c = e & 7;
        cp16(sb + SM_Q + r * AQ_STRIDE + (c << 4),
             qv_head + (qrow0 + r) * TD3 + (c << 3));
    }
    att_load_kv(sb + SM_KV0, qv_head, (size_t)b * TTOK, tid);
    CP_COMMIT();
    if (ntiles > 1) {
        att_load_kv(sb + SM_KV0 + KV_STG, qv_head, (size_t)b * TTOK + 64, tid);
    }
    CP_COMMIT();

    uint32_t qf[4][4];
    float O[8][4];
    #pragma unroll
    for (int n = 0; n < 8; n++)
        #pragma unroll
        for (int e = 0; e < 4; e++) O[n][e] = 0.f;
    float m0 = -1e30f, m1 = -1e30f, l0 = 0.f, l1 = 0.f;

    int bg = lane >> 3, brow = lane & 7;
    bool qloaded = false;

    for (int j = 0; j < ntiles; j++) {
        CP_WAIT1();                 // groups 0..j complete -> stage j (and Q) resident
        __syncthreads();            // all warps past stage (j-1) compute
        if (j + 2 < ntiles)
            att_load_kv(sb + SM_KV0 + (uint32_t)((j + 2) % 3) * KV_STG,
                        qv_head, (size_t)b * TTOK + (size_t)(j + 2) * 64, tid);
        CP_COMMIT();                // unconditional: keeps group arithmetic exact
        if (!qloaded) {
            qloaded = true;
            #pragma unroll
            for (int kc = 0; kc < 4; kc++) {
                uint32_t aoff = (uint32_t)((wid * 16 + (lane & 15)) * AQ_STRIDE
                                           + ((kc << 4) + ((lane >> 4) << 3)) * 2);
                ldsm4(qf[kc], sb + SM_Q + aoff);
            }
        }

        uint32_t kb = sb + SM_KV0 + (uint32_t)(j % 3) * KV_STG;

        // ---- S = Q K^T ----
        float S[8][4];
        #pragma unroll
        for (int n = 0; n < 8; n++)
            #pragma unroll
            for (int e = 0; e < 4; e++) S[n][e] = 0.f;
        #pragma unroll
        for (int p = 0; p < 4; p++) {
            #pragma unroll
            for (int kc = 0; kc < 4; kc++) {
                uint32_t koff = (uint32_t)(((p << 4) + ((bg >> 1) << 3) + brow) * AQ_STRIDE
                                           + ((kc << 4) + ((bg & 1) << 3)) * 2);
                uint32_t rh[4];
                ldsm4(rh, kb + koff);
                mma_f16(S[2*p],   qf[kc], rh[0], rh[1]);
                mma_f16(S[2*p+1], qf[kc], rh[2], rh[3]);
            }
        }

        // ---- scale + causal mask ----
        int row0 = qt * 128 + wid * 16 + (lane >> 2);
        int row1 = row0 + 8;
        int cbase = j * 64 + ((lane & 3) << 1);
        bool need_mask = (j >= 2 * qt);
        #pragma unroll
        for (int n = 0; n < 8; n++) {
            #pragma unroll
            for (int e = 0; e < 4; e++) S[n][e] *= 0.125f;
            if (need_mask) {
                int c0 = cbase + n * 8;
                if (c0     > row0) S[n][0] = -1e30f;
                if (c0 + 1 > row0) S[n][1] = -1e30f;
                if (c0     > row1) S[n][2] = -1e30f;
                if (c0 + 1 > row1) S[n][3] = -1e30f;
            }
        }

        // ---- online max + alpha ----
        float mr0 = -1e30f, mr1 = -1e30f;
        #pragma unroll
        for (int n = 0; n < 8; n++) {
            mr0 = fmaxf(mr0, fmaxf(S[n][0], S[n][1]));
            mr1 = fmaxf(mr1, fmaxf(S[n][2], S[n][3]));
        }
        mr0 = fmaxf(mr0, __shfl_xor_sync(0xffffffffu, mr0, 1));
        mr0 = fmaxf(mr0, __shfl_xor_sync(0xffffffffu, mr0, 2));
        mr1 = fmaxf(mr1, __shfl_xor_sync(0xffffffffu, mr1, 1));
        mr1 = fmaxf(mr1, __shfl_xor_sync(0xffffffffu, mr1, 2));
        float mn0 = fmaxf(m0, mr0), mn1 = fmaxf(m1, mr1);
        float alpha0 = __expf(m0 - mn0), alpha1 = __expf(m1 - mn1);
        m0 = mn0; m1 = mn1;
        #pragma unroll
        for (int n = 0; n < 8; n++) {
            O[n][0] *= alpha0; O[n][1] *= alpha0;
            O[n][2] *= alpha1; O[n][3] *= alpha1;
        }

        // ---- P = exp(S - m) via ex2.f16x2, fused with PV MMA ----
        float sum0 = 0.f, sum1 = 0.f;
        #pragma unroll
        for (int kc = 0; kc < 4; kc++) {
            uint32_t pf[4];
            pf[0] = ex2_h2((S[2*kc][0]   - mn0) * L2E, (S[2*kc][1]   - mn0) * L2E);
            pf[1] = ex2_h2((S[2*kc][2]   - mn1) * L2E, (S[2*kc][3]   - mn1) * L2E);
            pf[2] = ex2_h2((S[2*kc+1][0] - mn0) * L2E, (S[2*kc+1][1] - mn0) * L2E);
            pf[3] = ex2_h2((S[2*kc+1][2] - mn1) * L2E, (S[2*kc+1][3] - mn1) * L2E);
            float2 f0 = __half22float2(*(__half2*)&pf[0]);
            float2 f1 = __half22float2(*(__half2*)&pf[1]);
            float2 f2 = __half22float2(*(__half2*)&pf[2]);
            float2 f3 = __half22float2(*(__half2*)&pf[3]);
            sum0 += f0.x + f0.y + f2.x + f2.y;
            sum1 += f1.x + f1.y + f3.x + f3.y;
            #pragma unroll
            for (int np = 0; np < 4; np++) {
                uint32_t voff = (uint32_t)(((kc << 4) + ((bg & 1) << 3) + brow) * AQ_STRIDE
                                           + ((np << 4) + ((bg >> 1) << 3)) * 2);
                uint32_t rv[4];
                ldsm4t(rv, kb + VOFF + voff);
                mma_f16(O[2*np],   pf, rv[0], rv[1]);
                mma_f16(O[2*np+1], pf, rv[2], rv[3]);
            }
        }
        sum0 += __shfl_xor_sync(0xffffffffu, sum0, 1);
        sum0 += __shfl_xor_sync(0xffffffffu, sum0, 2);
        sum1 += __shfl_xor_sync(0xffffffffu, sum1, 1);
        sum1 += __shfl_xor_sync(0xffffffffu, sum1, 2);
        l0 = l0 * alpha0 + sum0;
        l1 = l1 * alpha1 + sum1;
    }

    float inv0 = 1.0f / l0, inv1 = 1.0f / l1;
    size_t row0g = qrow0 + wid * 16 + (lane >> 2);
    int colb = h * HDIM + ((lane & 3) << 1);
    #pragma unroll
    for (int n = 0; n < 8; n++) {
        int col = colb + n * 8;
        *(__half2*)(o16 + row0g * DDIM + col) =
            __floats2half2_rn(O[n][0] * inv0, O[n][1] * inv0);
        *(__half2*)(o16 + (row0g + 8) * DDIM + col) =
            __floats2half2_rn(O[n][2] * inv1, O[n][3] * inv1);
    }
}

extern "C" void kernel_launch(void* const* d_in, const int* in_sizes, int n_in,
                              void* d_out, int out_size) {
    const float* x      = (const float*)d_in[0];
    const float* ln1_g  = (const float*)d_in[1];
    const float* ln1_b  = (const float*)d_in[2];
    const float* ln2_g  = (const float*)d_in[3];
    const float* ln2_b  = (const float*)d_in[4];
    const float* w_qkv  = (const float*)d_in[5];
    const float* b_qkv  = (const float*)d_in[6];
    const float* w_o    = (const float*)d_in[7];
    const float* b_o    = (const float*)d_in[8];
    const float* w_fc1  = (const float*)d_in[9];
    const float* b_fc1  = (const float*)d_in[10];
    const float* w_fc2  = (const float*)d_in[11];
    const float* b_fc2  = (const float*)d_in[12];
    float* out = (float*)d_out;

    float* p_x1;
    __half *p_a16, *p_qv16, *p_h16, *p_wq, *p_wo, *p_w1, *p_w2;
    cudaGetSymbolAddress((void**)&p_x1,   g_x1);
    cudaGetSymbolAddress((void**)&p_a16,  g_a16);
    cudaGetSymbolAddress((void**)&p_qv16, g_qv16);
    cudaGetSymbolAddress((void**)&p_h16,  g_h16);
    cudaGetSymbolAddress((void**)&p_wq,   g_wq16);
    cudaGetSymbolAddress((void**)&p_wo,   g_wo16);
    cudaGetSymbolAddress((void**)&p_w1,   g_w116);
    cudaGetSymbolAddress((void**)&p_w2,   g_w216);

    cudaFuncSetAttribute(attn_tc, cudaFuncAttributeMaxDynamicSharedMemorySize, ATT_SMEM);
    cudaFuncSetAttribute(hmma_gemm<1>, cudaFuncAttributeMaxDynamicSharedMemorySize, GEMM_SMEM);
    cudaFuncSetAttribute(hmma_gemm<2>, cudaFuncAttributeMaxDynamicSharedMemorySize, GEMM_SMEM);
    cudaFuncSetAttribute(hmma_gemm<3>, cudaFuncAttributeMaxDynamicSharedMemorySize, GEMM_SMEM);

    static cudaStream_t s_side = nullptr;
    static cudaEvent_t ev_fork = nullptr, ev_ln = nullptr, ev_join = nullptr;
    if (s_side == nullptr) {
        cudaStreamCreateWithFlags(&s_side, cudaStreamNonBlocking);
        cudaEventCreateWithFlags(&ev_fork, cudaEventDisableTiming);
        cudaEventCreateWithFlags(&ev_ln,   cudaEventDisableTiming);
        cudaEventCreateWithFlags(&ev_join, cudaEventDisableTiming);
    }

    // fork: side stream does ln1 then wo/w1/w2 converts
    cudaEventRecord(ev_fork, (cudaStream_t)0);
    cudaStreamWaitEvent(s_side, ev_fork, 0);
    ln_h<<<BT, 256, 0, s_side>>>(x, ln1_g, ln1_b, p_a16);
    cudaEventRecord(ev_ln, s_side);
    wconv16<<<(DDIM * DDIM / 8 + 255) / 256, 256, 0, s_side>>>(w_o, p_wo, DDIM * DDIM / 8);
    wconv16<<<(4 * DDIM * DDIM / 8 + 255) / 256, 256, 0, s_side>>>(w_fc1, p_w1, 4 * DDIM * DDIM / 8);
    wconv16<<<(4 * DDIM * DDIM / 8 + 255) / 256, 256, 0, s_side>>>(w_fc2, p_w2, 4 * DDIM * DDIM / 8);
    cudaEventRecord(ev_join, s_side);

    // main stream
    wconv16<<<(3 * DDIM * DDIM / 8 + 255) / 256, 256>>>(w_qkv, p_wq, 3 * DDIM * DDIM / 8);
    cudaStreamWaitEvent((cudaStream_t)0, ev_ln, 0);
    hmma_gemm<3><<<dim3(3 * DDIM / 256, BT / 128), 256, GEMM_SMEM>>>(
        p_a16, p_wq, b_qkv, nullptr, nullptr, p_qv16, 3 * DDIM, DDIM);
    attn_tc<<<dim3(TTOK / 128, BB * NH), 256, ATT_SMEM>>>(p_qv16, p_a16);
    cudaStreamWaitEvent((cudaStream_t)0, ev_join, 0);
    hmma_gemm<2><<<dim3(DDIM / 256, BT / 128), 256, GEMM_SMEM>>>(
        p_a16, p_wo, b_o, x, p_x1, nullptr, DDIM, DDIM);
    ln_h<<<BT, 256>>>(p_x1, ln2_g, ln2_b, p_a16);
    hmma_gemm<1><<<dim3(4 * DDIM / 256, BT / 128), 256, GEMM_SMEM>>>(
        p_a16, p_w1, b_fc1, nullptr, nullptr, p_h16, 4 * DDIM, DDIM);
    hmma_gemm<2><<<dim3(DDIM / 256, BT / 128), 256, GEMM_SMEM>>>(
        p_h16, p_w2, b_fc2, p_x1, out, nullptr, DDIM, 4 * DDIM);
}

// round 16
// speedup vs baseline: 1.0016x; 1.0016x over previous
#include <cuda_runtime.h>
#include <cuda_fp16.h>
#include <math.h>
#include <stdint.h>

#define BB   2
#define TTOK 2048
#define DDIM 1024
#define NH   16
#define HDIM 64
#define BT   (BB*TTOK)   // 4096

// scratch (static device arrays)
__device__ float  g_x1 [BT * DDIM];
__device__ __half g_a16[BT * DDIM];
__device__ __half g_qv16[BT * 3 * DDIM];
__device__ __half g_h16[BT * 4 * DDIM];
__device__ __half g_wq16[3 * DDIM * DDIM];   // [K,N] fp16 weights
__device__ __half g_wo16[DDIM * DDIM];
__device__ __half g_w116[4 * DDIM * DDIM];
__device__ __half g_w216[4 * DDIM * DDIM];

__device__ __forceinline__ uint32_t s2u(const void* p) {
    uint32_t a;
    asm("{ .reg .u64 t; cvta.to.shared.u64 t, %1; cvt.u32.u64 %0, t; }" : "=r"(a) : "l"(p));
    return a;
}
__device__ __forceinline__ void cp16(uint32_t dst, const void* src) {
    asm volatile("cp.async.cg.shared.global [%0], [%1], 16;" :: "r"(dst), "l"(src));
}
#define CP_COMMIT() asm volatile("cp.async.commit_group;" ::: "memory")
#define CP_WAIT0()  asm volatile("cp.async.wait_group 0;" ::: "memory")

__device__ __forceinline__ void ldsm4(uint32_t* r, uint32_t addr) {
    asm volatile("ldmatrix.sync.aligned.m8n8.x4.shared.b16 {%0,%1,%2,%3}, [%4];"
                 : "=r"(r[0]), "=r"(r[1]), "=r"(r[2]), "=r"(r[3]) : "r"(addr));
}
__device__ __forceinline__ void ldsm4t(uint32_t* r, uint32_t addr) {
    asm volatile("ldmatrix.sync.aligned.m8n8.x4.trans.shared.b16 {%0,%1,%2,%3}, [%4];"
                 : "=r"(r[0]), "=r"(r[1]), "=r"(r[2]), "=r"(r[3]) : "r"(addr));
}
__device__ __forceinline__ void mma_f16(float* c, const uint32_t* a,
                                        uint32_t b0, uint32_t b1) {
    asm("mma.sync.aligned.m16n8k16.row.col.f32.f16.f16.f32 "
        "{%0,%1,%2,%3}, {%4,%5,%6,%7}, {%8,%9}, {%0,%1,%2,%3};"
        : "+f"(c[0]), "+f"(c[1]), "+f"(c[2]), "+f"(c[3])
        : "r"(a[0]), "r"(a[1]), "r"(a[2]), "r"(a[3]), "r"(b0), "r"(b1));
}
__device__ __forceinline__ uint32_t ex2_h2(float a0, float a1) {
    __half2 h = __floats2half2_rn(a0, a1);
    uint32_t r;
    asm("ex2.approx.f16x2 %0, %1;" : "=r"(r) : "r"(*(uint32_t*)&h));
    return r;
}

__device__ __forceinline__ float gelu_f(float x) {
    float x3 = x * x * x;
    return 0.5f * x * (1.0f + tanhf(0.7978845608028654f * (x + 0.044715f * x3)));
}

// streaming fp32 -> fp16 convert
__global__ void wconv16(const float* __restrict__ W, __half* __restrict__ O, int n8) {
    int idx = blockIdx.x * 256 + threadIdx.x;
    if (idx >= n8) return;
    size_t base = (size_t)idx * 8;
    float4 a = *(const float4*)(W + base);
    float4 b = *(const float4*)(W + base + 4);
    __half2 h[4];
    h[0] = __floats2half2_rn(a.x, a.y);
    h[1] = __floats2half2_rn(a.z, a.w);
    h[2] = __floats2half2_rn(b.x, b.y);
    h[3] = __floats2half2_rn(b.z, b.w);
    *(uint4*)(O + base) = *(uint4*)h;
}

// LayerNorm -> fp16
__global__ void ln_h(const float* __restrict__ x, const float* __restrict__ g,
                     const float* __restrict__ b, __half* __restrict__ o) {
    int row = blockIdx.x;
    int tid = threadIdx.x;
    float4 v = ((const float4*)(x + (size_t)row * DDIM))[tid];
    float s  = v.x + v.y + v.z + v.w;
    float ss = v.x*v.x + v.y*v.y + v.z*v.z + v.w*v.w;
    #pragma unroll
    for (int off = 16; off > 0; off >>= 1) {
        s  += __shfl_xor_sync(0xffffffffu, s,  off);
        ss += __shfl_xor_sync(0xffffffffu, ss, off);
    }
    __shared__ float rs[8], rss[8];
    int w = tid >> 5, ln = tid & 31;
    if (ln == 0) { rs[w] = s; rss[w] = ss; }
    __syncthreads();
    float tot = 0.f, tots = 0.f;
    #pragma unroll
    for (int i = 0; i < 8; i++) { tot += rs[i]; tots += rss[i]; }
    float mu  = tot * (1.0f / DDIM);
    float var = tots * (1.0f / DDIM) - mu * mu;
    float inv = rsqrtf(var + 1e-5f);
    float4 gg = ((const float4*)g)[tid];
    float4 bb = ((const float4*)b)[tid];
    float r0 = (v.x - mu) * inv * gg.x + bb.x;
    float r1 = (v.y - mu) * inv * gg.y + bb.y;
    float r2 = (v.z - mu) * inv * gg.z + bb.z;
    float r3 = (v.w - mu) * inv * gg.w + bb.w;
    size_t base = (size_t)row * DDIM + tid * 4;
    *(__half2*)(o + base)     = __floats2half2_rn(r0, r1);
    *(__half2*)(o + base + 2) = __floats2half2_rn(r2, r3);
}

// HMMA fp16 GEMM: C[M,N] = A[M,K] @ B[K,N] + bias   (B in [K,N] row-major)
// 128x256 block, 8 warps (2Mx4N), warp 64x64, K-chunk 128, 2-stage cp.async,
// manual fragment double-buffering across k16 steps.
#define AROWB  272
#define BROWB  528
#define OFF_A  0
#define OFF_B  (128*272)
#define STG    (128*272 + 128*528)       // 102400
#define GEMM_SMEM (2 * STG)              // 204800

__device__ __forceinline__ void load_stage(
    uint32_t st, const __half* __restrict__ A, const __half* __restrict__ B,
    int N, int K, int bm, int bn, int k0, int tid)
{
    #pragma unroll
    for (int j = 0; j < 8; j++) {
        int o = tid + (j << 8);
        int r = o >> 4, c = o & 15;
        cp16(st + OFF_A + (uint32_t)(r * AROWB + (c << 4)),
             A + (size_t)(bm + r) * K + k0 + (c << 3));
    }
    #pragma unroll
    for (int j = 0; j < 16; j++) {
        int o = tid + (j << 8);
        int r = o >> 5, c = o & 31;
        cp16(st + OFF_B + (uint32_t)(r * BROWB + (c << 4)),
             B + (size_t)(k0 + r) * N + bn + (c << 3));
    }
}

__device__ __forceinline__ void load_frags(
    uint32_t st, int ks, int wm, int wn, int arow, int acol, int bg, int brow,
    uint32_t aF[4][4], uint32_t bF[8][2])
{
    #pragma unroll
    for (int mi = 0; mi < 4; mi++) {
        uint32_t off = (uint32_t)(((wm << 6) + (mi << 4) + arow) * AROWB
                                  + ((ks << 4) + acol) * 2);
        ldsm4(aF[mi], st + OFF_A + off);
    }
    #pragma unroll
    for (int np = 0; np < 4; np++) {
        uint32_t off = (uint32_t)(((ks << 4) + ((bg & 1) << 3) + brow) * BROWB
                                  + ((wn << 6) + (np << 4) + ((bg >> 1) << 3)) * 2);
        uint32_t r[4];
        ldsm4t(r, st + OFF_B + off);
        bF[2*np][0]   = r[0]; bF[2*np][1]   = r[1];
        bF[2*np+1][0] = r[2]; bF[2*np+1][1] = r[3];
    }
}

template<int EPI>
__global__ void __launch_bounds__(256, 1) hmma_gemm(
    const __half* __restrict__ A, const __half* __restrict__ B,
    const float* __restrict__ bias, const float* __restrict__ res,
    float* __restrict__ Cf, __half* __restrict__ Ch, int N, int K)
{
    extern __shared__ __align__(1024) char smem[];
    uint32_t sb = s2u(smem);
    int tid = threadIdx.x, wid = tid >> 5, lane = tid & 31;
    int wm = wid & 1, wn = wid >> 1;
    int bm = blockIdx.y << 7, bn = blockIdx.x << 8;

    float acc[4][8][4];
    #pragma unroll
    for (int mi = 0; mi < 4; mi++)
        #pragma unroll
        for (int ni = 0; ni < 8; ni++)
            #pragma unroll
            for (int e = 0; e < 4; e++) acc[mi][ni][e] = 0.f;

    int nch = K >> 7;
    load_stage(sb, A, B, N, K, bm, bn, 0, tid);
    CP_COMMIT();

    int arow = lane & 15;
    int acol = (lane >> 4) << 3;
    int bg   = lane >> 3;
    int brow = lane & 7;

    uint32_t aF[2][4][4], bF[2][8][2];

    for (int i = 0; i < nch; i++) {
        CP_WAIT0();
        __syncthreads();
        if (i + 1 < nch) {
            load_stage(sb + (uint32_t)((i + 1) & 1) * STG,
                       A, B, N, K, bm, bn, (i + 1) << 7, tid);
            CP_COMMIT();
        }
        uint32_t st = sb + (uint32_t)(i & 1) * STG;
        load_frags(st, 0, wm, wn, arow, acol, bg, brow, aF[0], bF[0]);
        #pragma unroll
        for (int ks = 0; ks < 8; ks++) {
            int cur = ks & 1;
            if (ks < 7)
                load_frags(st, ks + 1, wm, wn, arow, acol, bg, brow,
                           aF[cur ^ 1], bF[cur ^ 1]);
            #pragma unroll
            for (int mi = 0; mi < 4; mi++)
                #pragma unroll
                for (int ni = 0; ni < 8; ni++)
                    mma_f16(acc[mi][ni], aF[cur][mi], bF[cur][ni][0], bF[cur][ni][1]);
        }
    }

    // epilogue touches only registers + global; no barrier needed
    #pragma unroll
    for (int mi = 0; mi < 4; mi++) {
        #pragma unroll
        for (int ni = 0; ni < 8; ni++) {
            int row0 = bm + (wm << 6) + (mi << 4) + (lane >> 2);
            int col  = bn + (wn << 6) + (ni << 3) + ((lane & 3) << 1);
            float b0 = __ldg(bias + col), b1 = __ldg(bias + col + 1);
            #pragma unroll
            for (int hf = 0; hf < 2; hf++) {
                int row = row0 + hf * 8;
                float v0 = acc[mi][ni][hf * 2 + 0] + b0;
                float v1 = acc[mi][ni][hf * 2 + 1] + b1;
                size_t oi = (size_t)row * N + col;
                if (EPI == 2) {
                    float2 rv = *(const float2*)(res + oi);
                    float2 ov; ov.x = v0 + rv.x; ov.y = v1 + rv.y;
                    *(float2*)(Cf + oi) = ov;
                } else {
                    float a0 = (EPI == 1) ? gelu_f(v0) : v0;
                    float a1 = (EPI == 1) ? gelu_f(v1) : v1;
                    *(__half2*)(Ch + oi) = __floats2half2_rn(a0, a1);
                }
            }
        }
    }
}

// fp16 flash attention: BQ=128 (8 warps x 16 rows), BK=64, hd=64
// 2 CTAs/SM (smem 55KB), 2-stage KV pipeline, fused ex2.f16x2 softmax.
#define AQ_STRIDE 144
#define SM_Q   0
#define SM_KV0 18432
#define KV_STG 18432
#define VOFF   9216
#define ATT_SMEM (SM_KV0 + 2 * KV_STG)   // 55296

__device__ __forceinline__ void att_load_kv(
    uint32_t base, const __half* __restrict__ qv, size_t kvrow0, int tid)
{
    const size_t TD3 = 3 * DDIM;
    #pragma unroll
    for (int i = 0; i < 4; i++) {
        int e = tid + (i << 8);
        int t = e >> 9;               // 0 K, 1 V
        int rem = e & 511;
        int r = rem >> 3, c = rem & 7;
        size_t off = (kvrow0 + r) * TD3 + (t ? 2 * DDIM : DDIM) + (c << 3);
        cp16(base + (t ? (uint32_t)VOFF : 0u) + r * AQ_STRIDE + (c << 4), qv + off);
    }
}

__global__ void __launch_bounds__(256, 2) attn_tc(
    const __half* __restrict__ qv, __half* __restrict__ o16)
{
    extern __shared__ __align__(1024) char smem[];
    uint32_t sb = s2u(smem);
    int qt = (int)gridDim.x - 1 - (int)blockIdx.x;
    int b  = blockIdx.y >> 4;
    int h  = blockIdx.y & 15;
    int tid = threadIdx.x, wid = tid >> 5, lane = tid & 31;
    const size_t TD3 = 3 * DDIM;
    size_t qrow0 = (size_t)b * TTOK + (size_t)qt * 128;
    const __half* qv_head = qv + h * HDIM;
    const float L2E = 1.4426950408889634f;

    #pragma unroll
    for (int i = 0; i < 4; i++) {
        int e = tid + (i << 8);
        int r = e >> 3, c = e & 7;
        cp16(sb + SM_Q + r * AQ_STRIDE + (c << 4),
             qv_head + (qrow0 + r) * TD3 + (c << 3));
    }
    att_load_kv(sb + SM_KV0, qv_head, (size_t)b * TTOK, tid);
    CP_COMMIT();

    uint32_t qf[4][4];
    float O[8][4];
    #pragma unroll
    for (int n = 0; n < 8; n++)
        #pragma unroll
        for (int e = 0; e < 4; e++) O[n][e] = 0.f;
    float m0 = -1e30f, m1 = -1e30f, l0 = 0.f, l1 = 0.f;

    int bg = lane >> 3, brow = lane & 7;
    int ntiles = 2 * qt + 2;
    bool qloaded = false;

    for (int j = 0; j < ntiles; j++) {
        CP_WAIT0();
        __syncthreads();
        if (j + 1 < ntiles) {
            att_load_kv(sb + SM_KV0 + (uint32_t)((j + 1) & 1) * KV_STG,
                        qv_head, (size_t)b * TTOK + (size_t)(j + 1) * 64, tid);
            CP_COMMIT();
        }
        if (!qloaded) {
            qloaded = true;
            #pragma unroll
            for (int kc = 0; kc < 4; kc++) {
                uint32_t aoff = (uint32_t)((wid * 16 + (lane & 15)) * AQ_STRIDE
                                           + ((kc << 4) + ((lane >> 4) << 3)) * 2);
                ldsm4(qf[kc], sb + SM_Q + aoff);
            }
        }

        uint32_t kb = sb + SM_KV0 + (uint32_t)(j & 1) * KV_STG;

        // ---- S = Q K^T ----
        float S[8][4];
        #pragma unroll
        for (int n = 0; n < 8; n++)
            #pragma unroll
            for (int e = 0; e < 4; e++) S[n][e] = 0.f;
        #pragma unroll
        for (int p = 0; p < 4; p++) {
            #pragma unroll
            for (int kc = 0; kc < 4; kc++) {
                uint32_t koff = (uint32_t)(((p << 4) + ((bg >> 1) << 3) + brow) * AQ_STRIDE
                                           + ((kc << 4) + ((bg & 1) << 3)) * 2);
                uint32_t rh[4];
                ldsm4(rh, kb + koff);
                mma_f16(S[2*p],   qf[kc], rh[0], rh[1]);
                mma_f16(S[2*p+1], qf[kc], rh[2], rh[3]);
            }
        }

        // ---- scale + causal mask ----
        int row0 = qt * 128 + wid * 16 + (lane >> 2);
        int row1 = row0 + 8;
        int cbase = j * 64 + ((lane & 3) << 1);
        bool need_mask = (j >= 2 * qt);
        #pragma unroll
        for (int n = 0; n < 8; n++) {
            #pragma unroll
            for (int e = 0; e < 4; e++) S[n][e] *= 0.125f;
            if (need_mask) {
                int c0 = cbase + n * 8;
                if (c0     > row0) S[n][0] = -1e30f;
                if (c0 + 1 > row0) S[n][1] = -1e30f;
                if (c0     > row1) S[n][2] = -1e30f;
                if (c0 + 1 > row1) S[n][3] = -1e30f;
            }
        }

        // ---- online max + alpha ----
        float mr0 = -1e30f, mr1 = -1e30f;
        #pragma unroll
        for (int n = 0; n < 8; n++) {
            mr0 = fmaxf(mr0, fmaxf(S[n][0], S[n][1]));
            mr1 = fmaxf(mr1, fmaxf(S[n][2], S[n][3]));
        }
        mr0 = fmaxf(mr0, __shfl_xor_sync(0xffffffffu, mr0, 1));
        mr0 = fmaxf(mr0, __shfl_xor_sync(0xffffffffu, mr0, 2));
        mr1 = fmaxf(mr1, __shfl_xor_sync(0xffffffffu, mr1, 1));
        mr1 = fmaxf(mr1, __shfl_xor_sync(0xffffffffu, mr1, 2));
        float mn0 = fmaxf(m0, mr0), mn1 = fmaxf(m1, mr1);
        float alpha0 = __expf(m0 - mn0), alpha1 = __expf(m1 - mn1);
        m0 = mn0; m1 = mn1;
        #pragma unroll
        for (int n = 0; n < 8; n++) {
            O[n][0] *= alpha0; O[n][1] *= alpha0;
            O[n][2] *= alpha1; O[n][3] *= alpha1;
        }

        // ---- P = exp(S - m) via ex2.f16x2, fused with PV MMA ----
        float sum0 = 0.f, sum1 = 0.f;
        #pragma unroll
        for (int kc = 0; kc < 4; kc++) {
            uint32_t pf[4];
            pf[0] = ex2_h2((S[2*kc][0]   - mn0) * L2E, (S[2*kc][1]   - mn0) * L2E);
            pf[1] = ex2_h2((S[2*kc][2]   - mn1) * L2E, (S[2*kc][3]   - mn1) * L2E);
            pf[2] = ex2_h2((S[2*kc+1][0] - mn0) * L2E, (S[2*kc+1][1] - mn0) * L2E);
            pf[3] = ex2_h2((S[2*kc+1][2] - mn1) * L2E, (S[2*kc+1][3] - mn1) * L2E);
            float2 f0 = __half22float2(*(__half2*)&pf[0]);
            float2 f1 = __half22float2(*(__half2*)&pf[1]);
            float2 f2 = __half22float2(*(__half2*)&pf[2]);
            float2 f3 = __half22float2(*(__half2*)&pf[3]);
            sum0 += f0.x + f0.y + f2.x + f2.y;
            sum1 += f1.x + f1.y + f3.x + f3.y;
            #pragma unroll
            for (int np = 0; np < 4; np++) {
                uint32_t voff = (uint32_t)(((kc << 4) + ((bg & 1) << 3) + brow) * AQ_STRIDE
                                           + ((np << 4) + ((bg >> 1) << 3)) * 2);
                uint32_t rv[4];
                ldsm4t(rv, kb + VOFF + voff);
                mma_f16(O[2*np],   pf, rv[0], rv[1]);
                mma_f16(O[2*np+1], pf, rv[2], rv[3]);
            }
        }
        sum0 += __shfl_xor_sync(0xffffffffu, sum0, 1);
        sum0 += __shfl_xor_sync(0xffffffffu, sum0, 2);
        sum1 += __shfl_xor_sync(0xffffffffu, sum1, 1);
        sum1 += __shfl_xor_sync(0xffffffffu, sum1, 2);
        l0 = l0 * alpha0 + sum0;
        l1 = l1 * alpha1 + sum1;
    }

    float inv0 = 1.0f / l0, inv1 = 1.0f / l1;
    size_t row0g = qrow0 + wid * 16 + (lane >> 2);
    int colb = h * HDIM + ((lane & 3) << 1);
    #pragma unroll
    for (int n = 0; n < 8; n++) {
        int col = colb + n * 8;
        *(__half2*)(o16 + row0g * DDIM + col) =
            __floats2half2_rn(O[n][0] * inv0, O[n][1] * inv0);
        *(__half2*)(o16 + (row0g + 8) * DDIM + col) =
            __floats2half2_rn(O[n][2] * inv1, O[n][3] * inv1);
    }
}

extern "C" void kernel_launch(void* const* d_in, const int* in_sizes, int n_in,
                              void* d_out, int out_size) {
    const float* x      = (const float*)d_in[0];
    const float* ln1_g  = (const float*)d_in[1];
    const float* ln1_b  = (const float*)d_in[2];
    const float* ln2_g  = (const float*)d_in[3];
    const float* ln2_b  = (const float*)d_in[4];
    const float* w_qkv  = (const float*)d_in[5];
    const float* b_qkv  = (const float*)d_in[6];
    const float* w_o    = (const float*)d_in[7];
    const float* b_o    = (const float*)d_in[8];
    const float* w_fc1  = (const float*)d_in[9];
    const float* b_fc1  = (const float*)d_in[10];
    const float* w_fc2  = (const float*)d_in[11];
    const float* b_fc2  = (const float*)d_in[12];
    float* out = (float*)d_out;

    float* p_x1;
    __half *p_a16, *p_qv16, *p_h16, *p_wq, *p_wo, *p_w1, *p_w2;
    cudaGetSymbolAddress((void**)&p_x1,   g_x1);
    cudaGetSymbolAddress((void**)&p_a16,  g_a16);
    cudaGetSymbolAddress((void**)&p_qv16, g_qv16);
    cudaGetSymbolAddress((void**)&p_h16,  g_h16);
    cudaGetSymbolAddress((void**)&p_wq,   g_wq16);
    cudaGetSymbolAddress((void**)&p_wo,   g_wo16);
    cudaGetSymbolAddress((void**)&p_w1,   g_w116);
    cudaGetSymbolAddress((void**)&p_w2,   g_w216);

    cudaFuncSetAttribute(attn_tc, cudaFuncAttributeMaxDynamicSharedMemorySize, ATT_SMEM);
    cudaFuncSetAttribute(hmma_gemm<1>, cudaFuncAttributeMaxDynamicSharedMemorySize, GEMM_SMEM);
    cudaFuncSetAttribute(hmma_gemm<2>, cudaFuncAttributeMaxDynamicSharedMemorySize, GEMM_SMEM);
    cudaFuncSetAttribute(hmma_gemm<3>, cudaFuncAttributeMaxDynamicSharedMemorySize, GEMM_SMEM);

    static cudaStream_t s_side = nullptr;
    static cudaEvent_t ev_fork = nullptr, ev_ln = nullptr, ev_join = nullptr;
    if (s_side == nullptr) {
        cudaStreamCreateWithFlags(&s_side, cudaStreamNonBlocking);
        cudaEventCreateWithFlags(&ev_fork, cudaEventDisableTiming);
        cudaEventCreateWithFlags(&ev_ln,   cudaEventDisableTiming);
        cudaEventCreateWithFlags(&ev_join, cudaEventDisableTiming);
    }

    // fork: side stream does ln1 then wo/w1/w2 converts
    cudaEventRecord(ev_fork, (cudaStream_t)0);
    cudaStreamWaitEvent(s_side, ev_fork, 0);
    ln_h<<<BT, 256, 0, s_side>>>(x, ln1_g, ln1_b, p_a16);
    cudaEventRecord(ev_ln, s_side);
    wconv16<<<(DDIM * DDIM / 8 + 255) / 256, 256, 0, s_side>>>(w_o, p_wo, DDIM * DDIM / 8);
    wconv16<<<(4 * DDIM * DDIM / 8 + 255) / 256, 256, 0, s_side>>>(w_fc1, p_w1, 4 * DDIM * DDIM / 8);
    wconv16<<<(4 * DDIM * DDIM / 8 + 255) / 256, 256, 0, s_side>>>(w_fc2, p_w2, 4 * DDIM * DDIM / 8);
    cudaEventRecord(ev_join, s_side);

    // main stream
    wconv16<<<(3 * DDIM * DDIM / 8 + 255) / 256, 256>>>(w_qkv, p_wq, 3 * DDIM * DDIM / 8);
    cudaStreamWaitEvent((cudaStream_t)0, ev_ln, 0);
    hmma_gemm<3><<<dim3(3 * DDIM / 256, BT / 128), 256, GEMM_SMEM>>>(
        p_a16, p_wq, b_qkv, nullptr, nullptr, p_qv16, 3 * DDIM, DDIM);
    attn_tc<<<dim3(TTOK / 128, BB * NH), 256, ATT_SMEM>>>(p_qv16, p_a16);
    cudaStreamWaitEvent((cudaStream_t)0, ev_join, 0);
    hmma_gemm<2><<<dim3(DDIM / 256, BT / 128), 256, GEMM_SMEM>>>(
        p_a16, p_wo, b_o, x, p_x1, nullptr, DDIM, DDIM);
    ln_h<<<BT, 256>>>(p_x1, ln2_g, ln2_b, p_a16);
    hmma_gemm<1><<<dim3(4 * DDIM / 256, BT / 128), 256, GEMM_SMEM>>>(
        p_a16, p_w1, b_fc1, nullptr, nullptr, p_h16, 4 * DDIM, DDIM);
    hmma_gemm<2><<<dim3(DDIM / 256, BT / 128), 256, GEMM_SMEM>>>(
        p_h16, p_w2, b_fc2, p_x1, out, nullptr, DDIM, 4 * DDIM);
}

// round 17
// speedup vs baseline: 1.0237x; 1.0221x over previous
#include <cuda_runtime.h>
#include <cuda_fp16.h>
#include <math.h>
#include <stdint.h>

#define BB   2
#define TTOK 2048
#define DDIM 1024
#define NH   16
#define HDIM 64
#define BT   (BB*TTOK)   // 4096

// scratch (static device arrays)
__device__ float  g_x1 [BT * DDIM];
__device__ __half g_a16[BT * DDIM];
__device__ __half g_qv16[BT * 3 * DDIM];
__device__ __half g_h16[BT * 4 * DDIM];
__device__ __half g_wq16[3 * DDIM * DDIM];   // [K,N] fp16 weights
__device__ __half g_wo16[DDIM * DDIM];
__device__ __half g_w116[4 * DDIM * DDIM];
__device__ __half g_w216[4 * DDIM * DDIM];

__device__ __forceinline__ uint32_t s2u(const void* p) {
    uint32_t a;
    asm("{ .reg .u64 t; cvta.to.shared.u64 t, %1; cvt.u32.u64 %0, t; }" : "=r"(a) : "l"(p));
    return a;
}
__device__ __forceinline__ void cp16(uint32_t dst, const void* src) {
    asm volatile("cp.async.cg.shared.global [%0], [%1], 16;" :: "r"(dst), "l"(src));
}
#define CP_COMMIT() asm volatile("cp.async.commit_group;" ::: "memory")
#define CP_WAIT0()  asm volatile("cp.async.wait_group 0;" ::: "memory")

__device__ __forceinline__ void ldsm4(uint32_t* r, uint32_t addr) {
    asm volatile("ldmatrix.sync.aligned.m8n8.x4.shared.b16 {%0,%1,%2,%3}, [%4];"
                 : "=r"(r[0]), "=r"(r[1]), "=r"(r[2]), "=r"(r[3]) : "r"(addr));
}
__device__ __forceinline__ void ldsm4t(uint32_t* r, uint32_t addr) {
    asm volatile("ldmatrix.sync.aligned.m8n8.x4.trans.shared.b16 {%0,%1,%2,%3}, [%4];"
                 : "=r"(r[0]), "=r"(r[1]), "=r"(r[2]), "=r"(r[3]) : "r"(addr));
}
__device__ __forceinline__ void mma_f16(float* c, const uint32_t* a,
                                        uint32_t b0, uint32_t b1) {
    asm("mma.sync.aligned.m16n8k16.row.col.f32.f16.f16.f32 "
        "{%0,%1,%2,%3}, {%4,%5,%6,%7}, {%8,%9}, {%0,%1,%2,%3};"
        : "+f"(c[0]), "+f"(c[1]), "+f"(c[2]), "+f"(c[3])
        : "r"(a[0]), "r"(a[1]), "r"(a[2]), "r"(a[3]), "r"(b0), "r"(b1));
}
__device__ __forceinline__ uint32_t ex2_h2(float a0, float a1) {
    __half2 h = __floats2half2_rn(a0, a1);
    uint32_t r;
    asm("ex2.approx.f16x2 %0, %1;" : "=r"(r) : "r"(*(uint32_t*)&h));
    return r;
}

// GELU with single-instruction tanh.approx.f32 (sm_75+)
__device__ __forceinline__ float gelu_f(float x) {
    float u = 0.7978845608028654f * (x + 0.044715f * x * x * x);
    float t;
    asm("tanh.approx.f32 %0, %1;" : "=f"(t) : "f"(u));
    return 0.5f * x * (1.0f + t);
}

// streaming fp32 -> fp16 convert
__global__ void wconv16(const float* __restrict__ W, __half* __restrict__ O, int n8) {
    int idx = blockIdx.x * 256 + threadIdx.x;
    if (idx >= n8) return;
    size_t base = (size_t)idx * 8;
    float4 a = *(const float4*)(W + base);
    float4 b = *(const float4*)(W + base + 4);
    __half2 h[4];
    h[0] = __floats2half2_rn(a.x, a.y);
    h[1] = __floats2half2_rn(a.z, a.w);
    h[2] = __floats2half2_rn(b.x, b.y);
    h[3] = __floats2half2_rn(b.z, b.w);
    *(uint4*)(O + base) = *(uint4*)h;
}

// LayerNorm -> fp16
__global__ void ln_h(const float* __restrict__ x, const float* __restrict__ g,
                     const float* __restrict__ b, __half* __restrict__ o) {
    int row = blockIdx.x;
    int tid = threadIdx.x;
    float4 v = ((const float4*)(x + (size_t)row * DDIM))[tid];
    float s  = v.x + v.y + v.z + v.w;
    float ss = v.x*v.x + v.y*v.y + v.z*v.z + v.w*v.w;
    #pragma unroll
    for (int off = 16; off > 0; off >>= 1) {
        s  += __shfl_xor_sync(0xffffffffu, s,  off);
        ss += __shfl_xor_sync(0xffffffffu, ss, off);
    }
    __shared__ float rs[8], rss[8];
    int w = tid >> 5, ln = tid & 31;
    if (ln == 0) { rs[w] = s; rss[w] = ss; }
    __syncthreads();
    float tot = 0.f, tots = 0.f;
    #pragma unroll
    for (int i = 0; i < 8; i++) { tot += rs[i]; tots += rss[i]; }
    float mu  = tot * (1.0f / DDIM);
    float var = tots * (1.0f / DDIM) - mu * mu;
    float inv = rsqrtf(var + 1e-5f);
    float4 gg = ((const float4*)g)[tid];
    float4 bb = ((const float4*)b)[tid];
    float r0 = (v.x - mu) * inv * gg.x + bb.x;
    float r1 = (v.y - mu) * inv * gg.y + bb.y;
    float r2 = (v.z - mu) * inv * gg.z + bb.z;
    float r3 = (v.w - mu) * inv * gg.w + bb.w;
    size_t base = (size_t)row * DDIM + tid * 4;
    *(__half2*)(o + base)     = __floats2half2_rn(r0, r1);
    *(__half2*)(o + base + 2) = __floats2half2_rn(r2, r3);
}

// HMMA fp16 GEMM: C[M,N] = A[M,K] @ B[K,N] + bias   (B in [K,N] row-major)
// 128x256 block, 8 warps (2Mx4N), warp 64x64, K-chunk 128, 2-stage cp.async,
// manual fragment double-buffering across k16 steps.
#define AROWB  272
#define BROWB  528
#define OFF_A  0
#define OFF_B  (128*272)
#define STG    (128*272 + 128*528)       // 102400
#define GEMM_SMEM (2 * STG)              // 204800

__device__ __forceinline__ void load_stage(
    uint32_t st, const __half* __restrict__ A, const __half* __restrict__ B,
    int N, int K, int bm, int bn, int k0, int tid)
{
    #pragma unroll
    for (int j = 0; j < 8; j++) {
        int o = tid + (j << 8);
        int r = o >> 4, c = o & 15;
        cp16(st + OFF_A + (uint32_t)(r * AROWB + (c << 4)),
             A + (size_t)(bm + r) * K + k0 + (c << 3));
    }
    #pragma unroll
    for (int j = 0; j < 16; j++) {
        int o = tid + (j << 8);
        int r = o >> 5, c = o & 31;
        cp16(st + OFF_B + (uint32_t)(r * BROWB + (c << 4)),
             B + (size_t)(k0 + r) * N + bn + (c << 3));
    }
}

__device__ __forceinline__ void load_frags(
    uint32_t st, int ks, int wm, int wn, int arow, int acol, int bg, int brow,
    uint32_t aF[4][4], uint32_t bF[8][2])
{
    #pragma unroll
    for (int mi = 0; mi < 4; mi++) {
        uint32_t off = (uint32_t)(((wm << 6) + (mi << 4) + arow) * AROWB
                                  + ((ks << 4) + acol) * 2);
        ldsm4(aF[mi], st + OFF_A + off);
    }
    #pragma unroll
    for (int np = 0; np < 4; np++) {
        uint32_t off = (uint32_t)(((ks << 4) + ((bg & 1) << 3) + brow) * BROWB
                                  + ((wn << 6) + (np << 4) + ((bg >> 1) << 3)) * 2);
        uint32_t r[4];
        ldsm4t(r, st + OFF_B + off);
        bF[2*np][0]   = r[0]; bF[2*np][1]   = r[1];
        bF[2*np+1][0] = r[2]; bF[2*np+1][1] = r[3];
    }
}

template<int EPI>
__global__ void __launch_bounds__(256, 1) hmma_gemm(
    const __half* __restrict__ A, const __half* __restrict__ B,
    const float* __restrict__ bias, const float* __restrict__ res,
    float* __restrict__ Cf, __half* __restrict__ Ch, int N, int K)
{
    extern __shared__ __align__(1024) char smem[];
    uint32_t sb = s2u(smem);
    int tid = threadIdx.x, wid = tid >> 5, lane = tid & 31;
    int wm = wid & 1, wn = wid >> 1;
    int bm = blockIdx.y << 7, bn = blockIdx.x << 8;

    float acc[4][8][4];
    #pragma unroll
    for (int mi = 0; mi < 4; mi++)
        #pragma unroll
        for (int ni = 0; ni < 8; ni++)
            #pragma unroll
            for (int e = 0; e < 4; e++) acc[mi][ni][e] = 0.f;

    int nch = K >> 7;
    load_stage(sb, A, B, N, K, bm, bn, 0, tid);
    CP_COMMIT();

    int arow = lane & 15;
    int acol = (lane >> 4) << 3;
    int bg   = lane >> 3;
    int brow = lane & 7;

    uint32_t aF[2][4][4], bF[2][8][2];

    for (int i = 0; i < nch; i++) {
        CP_WAIT0();
        __syncthreads();
        if (i + 1 < nch) {
            load_stage(sb + (uint32_t)((i + 1) & 1) * STG,
                       A, B, N, K, bm, bn, (i + 1) << 7, tid);
            CP_COMMIT();
        }
        uint32_t st = sb + (uint32_t)(i & 1) * STG;
        load_frags(st, 0, wm, wn, arow, acol, bg, brow, aF[0], bF[0]);
        #pragma unroll
        for (int ks = 0; ks < 8; ks++) {
            int cur = ks & 1;
            if (ks < 7)
                load_frags(st, ks + 1, wm, wn, arow, acol, bg, brow,
                           aF[cur ^ 1], bF[cur ^ 1]);
            #pragma unroll
            for (int mi = 0; mi < 4; mi++)
                #pragma unroll
                for (int ni = 0; ni < 8; ni++)
                    mma_f16(acc[mi][ni], aF[cur][mi], bF[cur][ni][0], bF[cur][ni][1]);
        }
    }

    // epilogue touches only registers + global; no barrier needed
    #pragma unroll
    for (int mi = 0; mi < 4; mi++) {
        #pragma unroll
        for (int ni = 0; ni < 8; ni++) {
            int row0 = bm + (wm << 6) + (mi << 4) + (lane >> 2);
            int col  = bn + (wn << 6) + (ni << 3) + ((lane & 3) << 1);
            float b0 = __ldg(bias + col), b1 = __ldg(bias + col + 1);
            #pragma unroll
            for (int hf = 0; hf < 2; hf++) {
                int row = row0 + hf * 8;
                float v0 = acc[mi][ni][hf * 2 + 0] + b0;
                float v1 = acc[mi][ni][hf * 2 + 1] + b1;
                size_t oi = (size_t)row * N + col;
                if (EPI == 2) {
                    float2 rv = *(const float2*)(res + oi);
                    float2 ov; ov.x = v0 + rv.x; ov.y = v1 + rv.y;
                    *(float2*)(Cf + oi) = ov;
                } else {
                    float a0 = (EPI == 1) ? gelu_f(v0) : v0;
                    float a1 = (EPI == 1) ? gelu_f(v1) : v1;
                    *(__half2*)(Ch + oi) = __floats2half2_rn(a0, a1);
                }
            }
        }
    }
}

// fp16 flash attention: BQ=128 (8 warps x 16 rows), BK=64, hd=64
// 2 CTAs/SM (smem 55KB), 2-stage KV pipeline, fused ex2.f16x2 softmax.
#define AQ_STRIDE 144
#define SM_Q   0
#define SM_KV0 18432
#define KV_STG 18432
#define VOFF   9216
#define ATT_SMEM (SM_KV0 + 2 * KV_STG)   // 55296

__device__ __forceinline__ void att_load_kv(
    uint32_t base, const __half* __restrict__ qv, size_t kvrow0, int tid)
{
    const size_t TD3 = 3 * DDIM;
    #pragma unroll
    for (int i = 0; i < 4; i++) {
        int e = tid + (i << 8);
        int t = e >> 9;               // 0 K, 1 V
        int rem = e & 511;
        int r = rem >> 3, c = rem & 7;
        size_t off = (kvrow0 + r) * TD3 + (t ? 2 * DDIM : DDIM) + (c << 3);
        cp16(base + (t ? (uint32_t)VOFF : 0u) + r * AQ_STRIDE + (c << 4), qv + off);
    }
}

__global__ void __launch_bounds__(256, 2) attn_tc(
    const __half* __restrict__ qv, __half* __restrict__ o16)
{
    extern __shared__ __align__(1024) char smem[];
    uint32_t sb = s2u(smem);
    int qt = (int)gridDim.x - 1 - (int)blockIdx.x;
    int b  = blockIdx.y >> 4;
    int h  = blockIdx.y & 15;
    int tid = threadIdx.x, wid = tid >> 5, lane = tid & 31;
    const size_t TD3 = 3 * DDIM;
    size_t qrow0 = (size_t)b * TTOK + (size_t)qt * 128;
    const __half* qv_head = qv + h * HDIM;
    const float L2E = 1.4426950408889634f;

    #pragma unroll
    for (int i = 0; i < 4; i++) {
        int e = tid + (i << 8);
        int r = e >> 3, c = e & 7;
        cp16(sb + SM_Q + r * AQ_STRIDE + (c << 4),
             qv_head + (qrow0 + r) * TD3 + (c << 3));
    }
    att_load_kv(sb + SM_KV0, qv_head, (size_t)b * TTOK, tid);
    CP_COMMIT();

    uint32_t qf[4][4];
    float O[8][4];
    #pragma unroll
    for (int n = 0; n < 8; n++)
        #pragma unroll
        for (int e = 0; e < 4; e++) O[n][e] = 0.f;
    float m0 = -1e30f, m1 = -1e30f, l0 = 0.f, l1 = 0.f;

    int bg = lane >> 3, brow = lane & 7;
    int ntiles = 2 * qt + 2;
    bool qloaded = false;

    for (int j = 0; j < ntiles; j++) {
        CP_WAIT0();
        __syncthreads();
        if (j + 1 < ntiles) {
            att_load_kv(sb + SM_KV0 + (uint32_t)((j + 1) & 1) * KV_STG,
                        qv_head, (size_t)b * TTOK + (size_t)(j + 1) * 64, tid);
            CP_COMMIT();
        }
        if (!qloaded) {
            qloaded = true;
            #pragma unroll
            for (int kc = 0; kc < 4; kc++) {
                uint32_t aoff = (uint32_t)((wid * 16 + (lane & 15)) * AQ_STRIDE
                                           + ((kc << 4) + ((lane >> 4) << 3)) * 2);
                ldsm4(qf[kc], sb + SM_Q + aoff);
            }
        }

        uint32_t kb = sb + SM_KV0 + (uint32_t)(j & 1) * KV_STG;

        // ---- S = Q K^T ----
        float S[8][4];
        #pragma unroll
        for (int n = 0; n < 8; n++)
            #pragma unroll
            for (int e = 0; e < 4; e++) S[n][e] = 0.f;
        #pragma unroll
        for (int p = 0; p < 4; p++) {
            #pragma unroll
            for (int kc = 0; kc < 4; kc++) {
                uint32_t koff = (uint32_t)(((p << 4) + ((bg >> 1) << 3) + brow) * AQ_STRIDE
                                           + ((kc << 4) + ((bg & 1) << 3)) * 2);
                uint32_t rh[4];
                ldsm4(rh, kb + koff);
                mma_f16(S[2*p],   qf[kc], rh[0], rh[1]);
                mma_f16(S[2*p+1], qf[kc], rh[2], rh[3]);
            }
        }

        // ---- scale + causal mask ----
        int row0 = qt * 128 + wid * 16 + (lane >> 2);
        int row1 = row0 + 8;
        int cbase = j * 64 + ((lane & 3) << 1);
        bool need_mask = (j >= 2 * qt);
        #pragma unroll
        for (int n = 0; n < 8; n++) {
            #pragma unroll
            for (int e = 0; e < 4; e++) S[n][e] *= 0.125f;
            if (need_mask) {
                int c0 = cbase + n * 8;
                if (c0     > row0) S[n][0] = -1e30f;
                if (c0 + 1 > row0) S[n][1] = -1e30f;
                if (c0     > row1) S[n][2] = -1e30f;
                if (c0 + 1 > row1) S[n][3] = -1e30f;
            }
        }

        // ---- online max + alpha ----
        float mr0 = -1e30f, mr1 = -1e30f;
        #pragma unroll
        for (int n = 0; n < 8; n++) {
            mr0 = fmaxf(mr0, fmaxf(S[n][0], S[n][1]));
            mr1 = fmaxf(mr1, fmaxf(S[n][2], S[n][3]));
        }
        mr0 = fmaxf(mr0, __shfl_xor_sync(0xffffffffu, mr0, 1));
        mr0 = fmaxf(mr0, __shfl_xor_sync(0xffffffffu, mr0, 2));
        mr1 = fmaxf(mr1, __shfl_xor_sync(0xffffffffu, mr1, 1));
        mr1 = fmaxf(mr1, __shfl_xor_sync(0xffffffffu, mr1, 2));
        float mn0 = fmaxf(m0, mr0), mn1 = fmaxf(m1, mr1);
        float alpha0 = __expf(m0 - mn0), alpha1 = __expf(m1 - mn1);
        m0 = mn0; m1 = mn1;
        #pragma unroll
        for (int n = 0; n < 8; n++) {
            O[n][0] *= alpha0; O[n][1] *= alpha0;
            O[n][2] *= alpha1; O[n][3] *= alpha1;
        }

        // ---- P = exp(S - m) via ex2.f16x2, fused with PV MMA ----
        float sum0 = 0.f, sum1 = 0.f;
        #pragma unroll
        for (int kc = 0; kc < 4; kc++) {
            uint32_t pf[4];
            pf[0] = ex2_h2((S[2*kc][0]   - mn0) * L2E, (S[2*kc][1]   - mn0) * L2E);
            pf[1] = ex2_h2((S[2*kc][2]   - mn1) * L2E, (S[2*kc][3]   - mn1) * L2E);
            pf[2] = ex2_h2((S[2*kc+1][0] - mn0) * L2E, (S[2*kc+1][1] - mn0) * L2E);
            pf[3] = ex2_h2((S[2*kc+1][2] - mn1) * L2E, (S[2*kc+1][3] - mn1) * L2E);
            float2 f0 = __half22float2(*(__half2*)&pf[0]);
            float2 f1 = __half22float2(*(__half2*)&pf[1]);
            float2 f2 = __half22float2(*(__half2*)&pf[2]);
            float2 f3 = __half22float2(*(__half2*)&pf[3]);
            sum0 += f0.x + f0.y + f2.x + f2.y;
            sum1 += f1.x + f1.y + f3.x + f3.y;
            #pragma unroll
            for (int np = 0; np < 4; np++) {
                uint32_t voff = (uint32_t)(((kc << 4) + ((bg & 1) << 3) + brow) * AQ_STRIDE
                                           + ((np << 4) + ((bg >> 1) << 3)) * 2);
                uint32_t rv[4];
                ldsm4t(rv, kb + VOFF + voff);
                mma_f16(O[2*np],   pf, rv[0], rv[1]);
                mma_f16(O[2*np+1], pf, rv[2], rv[3]);
            }
        }
        sum0 += __shfl_xor_sync(0xffffffffu, sum0, 1);
        sum0 += __shfl_xor_sync(0xffffffffu, sum0, 2);
        sum1 += __shfl_xor_sync(0xffffffffu, sum1, 1);
        sum1 += __shfl_xor_sync(0xffffffffu, sum1, 2);
        l0 = l0 * alpha0 + sum0;
        l1 = l1 * alpha1 + sum1;
    }

    float inv0 = 1.0f / l0, inv1 = 1.0f / l1;
    size_t row0g = qrow0 + wid * 16 + (lane >> 2);
    int colb = h * HDIM + ((lane & 3) << 1);
    #pragma unroll
    for (int n = 0; n < 8; n++) {
        int col = colb + n * 8;
        *(__half2*)(o16 + row0g * DDIM + col) =
            __floats2half2_rn(O[n][0] * inv0, O[n][1] * inv0);
        *(__half2*)(o16 + (row0g + 8) * DDIM + col) =
            __floats2half2_rn(O[n][2] * inv1, O[n][3] * inv1);
    }
}

extern "C" void kernel_launch(void* const* d_in, const int* in_sizes, int n_in,
                              void* d_out, int out_size) {
    const float* x      = (const float*)d_in[0];
    const float* ln1_g  = (const float*)d_in[1];
    const float* ln1_b  = (const float*)d_in[2];
    const float* ln2_g  = (const float*)d_in[3];
    const float* ln2_b  = (const float*)d_in[4];
    const float* w_qkv  = (const float*)d_in[5];
    const float* b_qkv  = (const float*)d_in[6];
    const float* w_o    = (const float*)d_in[7];
    const float* b_o    = (const float*)d_in[8];
    const float* w_fc1  = (const float*)d_in[9];
    const float* b_fc1  = (const float*)d_in[10];
    const float* w_fc2  = (const float*)d_in[11];
    const float* b_fc2  = (const float*)d_in[12];
    float* out = (float*)d_out;

    float* p_x1;
    __half *p_a16, *p_qv16, *p_h16, *p_wq, *p_wo, *p_w1, *p_w2;
    cudaGetSymbolAddress((void**)&p_x1,   g_x1);
    cudaGetSymbolAddress((void**)&p_a16,  g_a16);
    cudaGetSymbolAddress((void**)&p_qv16, g_qv16);
    cudaGetSymbolAddress((void**)&p_h16,  g_h16);
    cudaGetSymbolAddress((void**)&p_wq,   g_wq16);
    cudaGetSymbolAddress((void**)&p_wo,   g_wo16);
    cudaGetSymbolAddress((void**)&p_w1,   g_w116);
    cudaGetSymbolAddress((void**)&p_w2,   g_w216);

    cudaFuncSetAttribute(attn_tc, cudaFuncAttributeMaxDynamicSharedMemorySize, ATT_SMEM);
    cudaFuncSetAttribute(hmma_gemm<1>, cudaFuncAttributeMaxDynamicSharedMemorySize, GEMM_SMEM);
    cudaFuncSetAttribute(hmma_gemm<2>, cudaFuncAttributeMaxDynamicSharedMemorySize, GEMM_SMEM);
    cudaFuncSetAttribute(hmma_gemm<3>, cudaFuncAttributeMaxDynamicSharedMemorySize, GEMM_SMEM);

    static cudaStream_t s_side = nullptr;
    static cudaEvent_t ev_fork = nullptr, ev_ln = nullptr, ev_join = nullptr;
    if (s_side == nullptr) {
        cudaStreamCreateWithFlags(&s_side, cudaStreamNonBlocking);
        cudaEventCreateWithFlags(&ev_fork, cudaEventDisableTiming);
        cudaEventCreateWithFlags(&ev_ln,   cudaEventDisableTiming);
        cudaEventCreateWithFlags(&ev_join, cudaEventDisableTiming);
    }

    // fork: side stream does ln1 then wo/w1/w2 converts
    cudaEventRecord(ev_fork, (cudaStream_t)0);
    cudaStreamWaitEvent(s_side, ev_fork, 0);
    ln_h<<<BT, 256, 0, s_side>>>(x, ln1_g, ln1_b, p_a16);
    cudaEventRecord(ev_ln, s_side);
    wconv16<<<(DDIM * DDIM / 8 + 255) / 256, 256, 0, s_side>>>(w_o, p_wo, DDIM * DDIM / 8);
    wconv16<<<(4 * DDIM * DDIM / 8 + 255) / 256, 256, 0, s_side>>>(w_fc1, p_w1, 4 * DDIM * DDIM / 8);
    wconv16<<<(4 * DDIM * DDIM / 8 + 255) / 256, 256, 0, s_side>>>(w_fc2, p_w2, 4 * DDIM * DDIM / 8);
    cudaEventRecord(ev_join, s_side);

    // main stream
    wconv16<<<(3 * DDIM * DDIM / 8 + 255) / 256, 256>>>(w_qkv, p_wq, 3 * DDIM * DDIM / 8);
    cudaStreamWaitEvent((cudaStream_t)0, ev_ln, 0);
    hmma_gemm<3><<<dim3(3 * DDIM / 256, BT / 128), 256, GEMM_SMEM>>>(
        p_a16, p_wq, b_qkv, nullptr, nullptr, p_qv16, 3 * DDIM, DDIM);
    attn_tc<<<dim3(TTOK / 128, BB * NH), 256, ATT_SMEM>>>(p_qv16, p_a16);
    cudaStreamWaitEvent((cudaStream_t)0, ev_join, 0);
    hmma_gemm<2><<<dim3(DDIM / 256, BT / 128), 256, GEMM_SMEM>>>(
        p_a16, p_wo, b_o, x, p_x1, nullptr, DDIM, DDIM);
    ln_h<<<BT, 256>>>(p_x1, ln2_g, ln2_b, p_a16);
    hmma_gemm<1><<<dim3(4 * DDIM / 256, BT / 128), 256, GEMM_SMEM>>>(
        p_a16, p_w1, b_fc1, nullptr, nullptr, p_h16, 4 * DDIM, DDIM);
    hmma_gemm<2><<<dim3(DDIM / 256, BT / 128), 256, GEMM_SMEM>>>(
        p_h16, p_w2, b_fc2, p_x1, out, nullptr, DDIM, 4 * DDIM);
}